// round 14
// baseline (speedup 1.0000x reference)
#include <cuda_runtime.h>
#include <math.h>

typedef unsigned long long ull;

#define NQ 20000
#define KN 32
#define FULLM 0xffffffffu

__device__ float g_pm[NQ * 64];
__device__ float g_agg[NQ * 192];
__device__ float g_gate[NQ * 192];

// ---------- packed f32x2 helpers ----------
__device__ __forceinline__ ull pk2(float lo, float hi) {
    ull r; asm("mov.b64 %0, {%1, %2};" : "=l"(r) : "f"(lo), "f"(hi)); return r;
}
__device__ __forceinline__ void upk2(ull v, float& lo, float& hi) {
    asm("mov.b64 {%0, %1}, %2;" : "=f"(lo), "=f"(hi) : "l"(v));
}
__device__ __forceinline__ ull fma2(ull a, ull b, ull c) {
    ull d; asm("fma.rn.f32x2 %0, %1, %2, %3;" : "=l"(d) : "l"(a), "l"(b), "l"(c)); return d;
}

__device__ __forceinline__ float fast_atan2_pi(float y, float x) {
    float ax = fabsf(x);
    float mx = fmaxf(ax, y);
    float mn = fminf(ax, y);
    float a = __fdividef(mn, fmaxf(mx, 1e-38f));
    float s = a * a;
    float r = -0.01172120f;
    r = fmaf(r, s, 0.05265332f);
    r = fmaf(r, s, -0.11643287f);
    r = fmaf(r, s, 0.19354346f);
    r = fmaf(r, s, -0.33262347f);
    r = fmaf(r, s, 0.99997726f);
    r = r * a;
    r = (y > ax) ? (1.57079632679f - r) : r;
    r = (x < 0.f) ? (3.14159265359f - r) : r;
    return r * 0.31830988618379067f;
}

__device__ __forceinline__ float angle_pi(float axx, float ayy, float azz,
                                          float bxx, float byy, float bzz) {
    float dt = axx * bxx + ayy * byy + azz * bzz;
    float cx = ayy * bzz - azz * byy;
    float cy = azz * bxx - axx * bzz;
    float cz = axx * byy - ayy * bxx;
    float xn = sqrtf(cx * cx + cy * cy + cz * cz);
    return fast_atan2_pi(xn, dt);
}

// ======= Kernel 1: gather-mean + PPF -> L1 -> L2 -> mean -> L3 (R11 exact + coalesced agg) =======
#define F_SW1 0
#define F_SB1 256
#define F_SB2 320
#define F_SB3 384
#define F_W2T 448                 // 64 x 68 [i*68+j]
#define F_W3T 4800                // 64 x 68 [i*68+o]
#define F_WARP 9152               // per warp: 576 floats (gather sc / h-stage / hbar)
#define F_SMF (F_WARP + 16 * 576)

__global__ __launch_bounds__(512, 1)
void fused_kernel(const float* __restrict__ q_pts,
                  const float* __restrict__ s_pts,
                  const float* __restrict__ s_feats,
                  const int* __restrict__ nbr,
                  const float* __restrict__ normals,
                  const float* __restrict__ W1, const float* __restrict__ b1,
                  const float* __restrict__ W2, const float* __restrict__ b2,
                  const float* __restrict__ W3, const float* __restrict__ b3) {
    extern __shared__ float sm[];
    const int tid = threadIdx.x;
    for (int i = tid; i < 256; i += 512) sm[F_SW1 + i] = W1[i];
    for (int i = tid; i < 64; i += 512) {
        sm[F_SB1 + i] = b1[i]; sm[F_SB2 + i] = b2[i]; sm[F_SB3 + i] = b3[i];
    }
    for (int l = tid; l < 4096; l += 512) {
        int j = l >> 6, i = l & 63;
        sm[F_W2T + i * 68 + j] = W2[l];
    }
    for (int l = tid; l < 4096; l += 512) {
        int o = l >> 6, i = l & 63;
        sm[F_W3T + i * 68 + o] = W3[l];
    }
    __syncthreads();

    const int w = tid >> 5, lane = tid & 31;
    float* hs = sm + F_WARP + w * 576;   // [16][36] h-stage; gather scratch; hbar
    float* shbf = hs;
    const int j0 = (lane >> 2) * 8;
    const int k0 = (lane & 3) * 8;

    const int o0 = lane * 4;
    const int o1 = (lane < 16) ? (lane + 32) * 4 : (lane - 16) * 4;
    const bool c1a = (lane < 16);
    const int o2 = (lane + 16) * 4;

    int q = blockIdx.x * 16 + w;
    if (q >= NQ) return;
    int idxk = nbr[q * KN + lane];

    for (; q < NQ; q += 148 * 16) {
        const int q_next = q + 148 * 16;
        int idx_next = 0;
        if (q_next < NQ) idx_next = nbr[q_next * KN + lane];

        // ---------------- gather-sum of s_feats over K ----------------
        {
            float4 a0 = {0,0,0,0}, a1 = {0,0,0,0}, a2 = {0,0,0,0};
#pragma unroll 4
            for (int t = 0; t < 16; t++) {
                int ra = __shfl_sync(FULLM, idxk, 2 * t);
                int rb = __shfl_sync(FULLM, idxk, 2 * t + 1);
                const float* pa = s_feats + (size_t)ra * 192;
                const float* pb = s_feats + (size_t)rb * 192;
                float4 v;
                v = *(const float4*)(pa + o0);
                a0.x += v.x; a0.y += v.y; a0.z += v.z; a0.w += v.w;
                v = *(const float4*)((c1a ? pa : pb) + o1);
                a1.x += v.x; a1.y += v.y; a1.z += v.z; a1.w += v.w;
                v = *(const float4*)(pb + o2);
                a2.x += v.x; a2.y += v.y; a2.z += v.z; a2.w += v.w;
            }
            float4* sc4 = (float4*)hs;
            sc4[lane] = a0; sc4[lane + 32] = a1; sc4[lane + 64] = a2;
        }
        __syncwarp();
        // combine even/odd halves; coalesced LDS + fully-coalesced STG.32
        {
            const float inv = 1.f / KN;
            float* dst = g_agg + (size_t)q * 192;
#pragma unroll
            for (int m = 0; m < 6; m++) {
                int e = lane + 32 * m;
                dst[e] = (hs[e] + hs[e + 192]) * inv;
            }
        }
        __syncwarp();

        // ---------------- PPF features ----------------
        const int idx0 = __shfl_sync(FULLM, idxk, 0);
        const float px = q_pts[q * 3 + 0], py = q_pts[q * 3 + 1], pz = q_pts[q * 3 + 2];
        const float pnx = normals[idx0 * 3 + 0], pny = normals[idx0 * 3 + 1], pnz = normals[idx0 * 3 + 2];
        const float sx = s_pts[idxk * 3 + 0], sy = s_pts[idxk * 3 + 1], sz = s_pts[idxk * 3 + 2];
        const float nnx = normals[idxk * 3 + 0], nny = normals[idxk * 3 + 1], nnz = normals[idxk * 3 + 2];

        const float vx = sx - px, vy = sy - py, vz = sz - pz;
        const float dpp = sqrtf(vx * vx + vy * vy + vz * vz);
        const float a1 = angle_pi(pnx, pny, pnz, vx, vy, vz);
        const float a2 = angle_pi(nnx, nny, nnz, vx, vy, vz);
        const float a3 = angle_pi(pnx, pny, pnz, nnx, nny, nnz);

        // ---------------- L2 GEMM: acc[jj][kp], k-pairs packed ----------------
        ull acc[8][4];
#pragma unroll
        for (int jj = 0; jj < 8; jj++) {
            float bv = sm[F_SB2 + j0 + jj];
            ull bp = pk2(bv, bv);
#pragma unroll
            for (int kp = 0; kp < 4; kp++) acc[jj][kp] = bp;
        }

#pragma unroll
        for (int p = 0; p < 4; p++) {
            const float4* w1v = (const float4*)(sm + F_SW1) + p * 16;
            const float* b1p = sm + F_SB1 + p * 16;
#pragma unroll
            for (int ii = 0; ii < 16; ii++) {
                float4 wv = w1v[ii];
                float v = b1p[ii];
                v = fmaf(dpp, wv.x, v);
                v = fmaf(a1, wv.y, v);
                v = fmaf(a2, wv.z, v);
                v = fmaf(a3, wv.w, v);
                hs[ii * 36 + lane] = fmaxf(v, 0.f);
            }
            __syncwarp();
#pragma unroll 4
            for (int ii = 0; ii < 16; ii++) {
                const float* wr = sm + F_W2T + (p * 16 + ii) * 68 + j0;
                float4 wa = *(const float4*)wr;
                float4 wb = *(const float4*)(wr + 4);
                const float* hr = hs + ii * 36 + k0;
                ulonglong2 hA = *(const ulonglong2*)hr;
                ulonglong2 hB = *(const ulonglong2*)(hr + 4);
                ull h0 = hA.x, h1 = hA.y, h2 = hB.x, h3 = hB.y;
                float wvv[8] = {wa.x, wa.y, wa.z, wa.w, wb.x, wb.y, wb.z, wb.w};
#pragma unroll
                for (int jj = 0; jj < 8; jj++) {
                    ull wd = pk2(wvv[jj], wvv[jj]);
                    acc[jj][0] = fma2(wd, h0, acc[jj][0]);
                    acc[jj][1] = fma2(wd, h1, acc[jj][1]);
                    acc[jj][2] = fma2(wd, h2, acc[jj][2]);
                    acc[jj][3] = fma2(wd, h3, acc[jj][3]);
                }
            }
            __syncwarp();
        }

        float o8[8];
#pragma unroll
        for (int jj = 0; jj < 8; jj++) {
            float s = 0.f;
#pragma unroll
            for (int kp = 0; kp < 4; kp++) {
                float lo, hi; upk2(acc[jj][kp], lo, hi);
                s += fmaxf(lo, 0.f) + fmaxf(hi, 0.f);
            }
            o8[jj] = s;
        }
#pragma unroll
        for (int u = 0; u < 8; u++) {
            o8[u] += __shfl_xor_sync(FULLM, o8[u], 1);
            o8[u] += __shfl_xor_sync(FULLM, o8[u], 2);
        }
        if ((lane & 3) == 0) {
            const float inv = 1.f / KN;
#pragma unroll
            for (int u = 0; u < 8; u++) shbf[j0 + u] = o8[u] * inv;
        }
        __syncwarp();

        // L3 on the mean: pm[64] -> global
        {
            float c0 = sm[F_SB3 + lane], c1 = sm[F_SB3 + lane + 32];
#pragma unroll 8
            for (int i = 0; i < 64; i++) {
                float hv = shbf[i];
                c0 = fmaf(hv, sm[F_W3T + i * 68 + lane], c0);
                c1 = fmaf(hv, sm[F_W3T + i * 68 + lane + 32], c1);
            }
            g_pm[q * 64 + lane] = c0;
            g_pm[q * 64 + lane + 32] = c1;
        }
        __syncwarp();
        idxk = idx_next;
    }
}

// ============ Kernel 2a: batched gate -> g_gate (2 CTAs/SM) ============
#define GA_WGT 0                  // 64*196 [j*196+o]
#define GA_BG  12544              // 192
#define GA_PM  12736              // 64*33 [j*33+q]
#define GA_GATE 14848             // 32*197 [q*197+o]
#define GA_SMF 21152              // 84.6 KB

#define GA_GRID 296

__global__ __launch_bounds__(512, 2)
void gate_kernel(const float* __restrict__ Wg, const float* __restrict__ bg) {
    extern __shared__ float sm[];
    const int tid = threadIdx.x;
    for (int l = tid; l < 12288; l += 512) {
        int o = l >> 6, j = l & 63;
        sm[GA_WGT + j * 196 + o] = Wg[l];
    }
    for (int l = tid; l < 192; l += 512) sm[GA_BG + l] = bg[l];
    __syncthreads();

    for (int base = blockIdx.x * 32; base < NQ; base += GA_GRID * 32) {
        // stage pm tile [64 j][32 q]
        {
            const float* psrc = g_pm + (size_t)base * 64;
            for (int e = tid; e < 2048; e += 512) {
                sm[GA_PM + (e & 63) * 33 + (e >> 6)] = psrc[e];
            }
        }
        __syncthreads();

        // gate: thread (q = tid&31, og) -> 12 o
        {
            const int ql = tid & 31, ob2 = (tid >> 5) * 12;
            ull ga[6];
#pragma unroll
            for (int s = 0; s < 6; s++) ga[s] = *(const ull*)(sm + GA_BG + ob2 + 2 * s);
#pragma unroll 4
            for (int j = 0; j < 64; j++) {
                float pv = sm[GA_PM + j * 33 + ql];
                ull pp = pk2(pv, pv);
                const float* wr = sm + GA_WGT + j * 196 + ob2;
                ulonglong2 wA = *(const ulonglong2*)wr;
                ulonglong2 wB = *(const ulonglong2*)(wr + 4);
                ulonglong2 wC = *(const ulonglong2*)(wr + 8);
                ga[0] = fma2(wA.x, pp, ga[0]); ga[1] = fma2(wA.y, pp, ga[1]);
                ga[2] = fma2(wB.x, pp, ga[2]); ga[3] = fma2(wB.y, pp, ga[3]);
                ga[4] = fma2(wC.x, pp, ga[4]); ga[5] = fma2(wC.y, pp, ga[5]);
            }
            float* gr = sm + GA_GATE + ql * 197 + ob2;
#pragma unroll
            for (int s = 0; s < 6; s++) {
                float lo, hi; upk2(ga[s], lo, hi);
                gr[2 * s + 0] = __fdividef(1.f, 1.f + __expf(-lo));
                gr[2 * s + 1] = __fdividef(1.f, 1.f + __expf(-hi));
            }
        }
        __syncthreads();

        // coalesced write to g_gate
        {
            float* gdst = g_gate + (size_t)base * 192;
            for (int e = tid; e < 6144; e += 512) {
                gdst[e] = sm[GA_GATE + (e / 192) * 197 + (e % 192)];
            }
        }
        __syncthreads();
    }
}

// ==== Kernel 2b: Wv GEMM + gate apply + coalesced store (384 thr, 2 CTAs/SM) ====
#define WB_NW 12
#define WB_WVT 0                  // 64*196 [d*196+o]
#define WB_AGG 12544              // 12 warps * 512 floats (256 ull) [d*4+t]
#define WB_SC  18688              // 12 warps * 608 floats
#define WB_SMF 25984              // 103.9 KB

#define WB_GRID 296

__global__ __launch_bounds__(384, 2)
void wv_out_kernel(const float* __restrict__ Wv, float* __restrict__ out) {
    extern __shared__ float sm[];
    const int tid = threadIdx.x;
    for (int l = tid; l < 12288; l += 384) {
        int o = l >> 6, d = l & 63;
        sm[WB_WVT + d * 196 + o] = Wv[l];
    }
    __syncthreads();

    const int w = tid >> 5, lane = tid & 31;
    ull* ag = (ull*)(sm + WB_AGG) + w * 256;
    float* scw = sm + WB_SC + w * 608;
    const int ob = lane * 6;

    for (int base = blockIdx.x * 24; base < NQ; base += WB_GRID * 24) {
        const int q0 = base + w, q1 = base + w + WB_NW;
        const int q0c = (q0 < NQ) ? q0 : (NQ - 1);
        const int q1c = (q1 < NQ) ? q1 : (NQ - 1);

        // ---- coalesced load of both agg rows into scw, then repack to ag ----
        {
            const ull* a0 = (const ull*)(g_agg + (size_t)q0c * 192);   // 96 ull
            const ull* a1 = (const ull*)(g_agg + (size_t)q1c * 192);
            ull* s0 = (ull*)scw;         // q0 raw: 96 ull = floats [0:192)
            ull* s1 = s0 + 96;           // q1 raw: floats [192:384)
            s0[lane] = a0[lane];
            s0[lane + 32] = a0[lane + 32];
            s0[lane + 64] = a0[lane + 64];
            s1[lane] = a1[lane];
            s1[lane + 32] = a1[lane + 32];
            s1[lane + 64] = a1[lane + 64];
            __syncwarp();
            const float* f0 = scw;
            const float* f1 = scw + 192;
#pragma unroll
            for (int u = 0; u < 6; u++) {
                int f = lane * 6 + u;
                ag[(2 * lane + u / 3) * 4 + (u % 3)] = pk2(f0[f], f1[f]);
            }
        }
        // load gates (L2-hot)
        float gt0[6], gt1[6];
        {
            const float* p0 = g_gate + (size_t)q0c * 192 + ob;
            const float* p1 = g_gate + (size_t)q1c * 192 + ob;
#pragma unroll
            for (int s = 0; s < 6; s++) { gt0[s] = p0[s]; gt1[s] = p1[s]; }
        }
        __syncwarp();

        // Wv GEMM, (q0,q1) packed in f32x2 lanes
        ull acc2[6][3];
#pragma unroll
        for (int oo = 0; oo < 6; oo++)
#pragma unroll
            for (int t = 0; t < 3; t++) acc2[oo][t] = 0ull;
#pragma unroll 2
        for (int d = 0; d < 64; d++) {
            const float* wp = sm + WB_WVT + d * 196 + ob;
            float2 w01 = *(const float2*)wp;
            float2 w23 = *(const float2*)(wp + 2);
            float2 w45 = *(const float2*)(wp + 4);
            ulonglong2 t01 = *(const ulonglong2*)(ag + d * 4);
            ull t2 = ag[d * 4 + 2];
            float wv6[6] = {w01.x, w01.y, w23.x, w23.y, w45.x, w45.y};
#pragma unroll
            for (int oo = 0; oo < 6; oo++) {
                ull wd = pk2(wv6[oo], wv6[oo]);
                acc2[oo][0] = fma2(wd, t01.x, acc2[oo][0]);
                acc2[oo][1] = fma2(wd, t01.y, acc2[oo][1]);
                acc2[oo][2] = fma2(wd, t2, acc2[oo][2]);
            }
        }

        // q0: stage (19-stride, conflict-free) + coalesced store
        if (q0 < NQ) {
#pragma unroll
            for (int oo = 0; oo < 6; oo++) {
                float x0, x1, y0, y1, z0, z1;
                upk2(acc2[oo][0], x0, x1);
                upk2(acc2[oo][1], y0, y1);
                upk2(acc2[oo][2], z0, z1);
                (void)x1; (void)y1; (void)z1;
                int b = 19 * lane + 3 * oo;
                scw[b + 0] = x0 * gt0[oo];
                scw[b + 1] = y0 * gt0[oo];
                scw[b + 2] = z0 * gt0[oo];
            }
            __syncwarp();
            float* ob0 = out + (size_t)q0 * 576;
#pragma unroll
            for (int i = 0; i < 18; i++) {
                int e = lane + 32 * i;
                ob0[e] = scw[e + e / 18];
            }
        }
        __syncwarp();

        // q1
        if (q1 < NQ) {
#pragma unroll
            for (int oo = 0; oo < 6; oo++) {
                float x0, x1, y0, y1, z0, z1;
                upk2(acc2[oo][0], x0, x1);
                upk2(acc2[oo][1], y0, y1);
                upk2(acc2[oo][2], z0, z1);
                (void)x0; (void)y0; (void)z0;
                int b = 19 * lane + 3 * oo;
                scw[b + 0] = x1 * gt1[oo];
                scw[b + 1] = y1 * gt1[oo];
                scw[b + 2] = z1 * gt1[oo];
            }
            __syncwarp();
            float* ob1 = out + (size_t)q1 * 576;
#pragma unroll
            for (int i = 0; i < 18; i++) {
                int e = lane + 32 * i;
                ob1[e] = scw[e + e / 18];
            }
        }
        __syncwarp();
    }
}

extern "C" void kernel_launch(void* const* d_in, const int* in_sizes, int n_in,
                              void* d_out, int out_size) {
    const float* q_pts   = (const float*)d_in[0];
    const float* s_pts   = (const float*)d_in[1];
    const float* s_feats = (const float*)d_in[2];
    const int*   nbr     = (const int*)  d_in[3];
    const float* normals = (const float*)d_in[4];
    const float* W1 = (const float*)d_in[5];
    const float* b1 = (const float*)d_in[6];
    const float* W2 = (const float*)d_in[7];
    const float* b2 = (const float*)d_in[8];
    const float* W3 = (const float*)d_in[9];
    const float* b3 = (const float*)d_in[10];
    const float* Wg = (const float*)d_in[11];
    const float* bg = (const float*)d_in[12];
    const float* Wv = (const float*)d_in[13];
    float* out = (float*)d_out;

    size_t smem1 = F_SMF * sizeof(float);    // ~73 KB
    size_t smem2a = GA_SMF * sizeof(float);  // ~85 KB
    size_t smem2b = WB_SMF * sizeof(float);  // ~104 KB
    cudaFuncSetAttribute(fused_kernel,
                         cudaFuncAttributeMaxDynamicSharedMemorySize, (int)smem1);
    cudaFuncSetAttribute(gate_kernel,
                         cudaFuncAttributeMaxDynamicSharedMemorySize, (int)smem2a);
    cudaFuncSetAttribute(wv_out_kernel,
                         cudaFuncAttributeMaxDynamicSharedMemorySize, (int)smem2b);

    fused_kernel<<<148, 512, smem1>>>(q_pts, s_pts, s_feats, nbr, normals,
                                      W1, b1, W2, b2, W3, b3);
    gate_kernel<<<GA_GRID, 512, smem2a>>>(Wg, bg);
    wv_out_kernel<<<WB_GRID, 384, smem2b>>>(Wv, out);
}

// round 15
// speedup vs baseline: 1.5742x; 1.5742x over previous
#include <cuda_runtime.h>
#include <math.h>

typedef unsigned long long ull;

#define NQ 20000
#define KN 32
#define FULLM 0xffffffffu

__device__ float g_pm[NQ * 64];
__device__ float g_agg[NQ * 192];
__device__ float g_gate[NQ * 192];

// ---------- packed f32x2 helpers ----------
__device__ __forceinline__ ull pk2(float lo, float hi) {
    ull r; asm("mov.b64 %0, {%1, %2};" : "=l"(r) : "f"(lo), "f"(hi)); return r;
}
__device__ __forceinline__ void upk2(ull v, float& lo, float& hi) {
    asm("mov.b64 {%0, %1}, %2;" : "=f"(lo), "=f"(hi) : "l"(v));
}
__device__ __forceinline__ ull fma2(ull a, ull b, ull c) {
    ull d; asm("fma.rn.f32x2 %0, %1, %2, %3;" : "=l"(d) : "l"(a), "l"(b), "l"(c)); return d;
}

__device__ __forceinline__ float fast_atan2_pi(float y, float x) {
    float ax = fabsf(x);
    float mx = fmaxf(ax, y);
    float mn = fminf(ax, y);
    float a = __fdividef(mn, fmaxf(mx, 1e-38f));
    float s = a * a;
    float r = -0.01172120f;
    r = fmaf(r, s, 0.05265332f);
    r = fmaf(r, s, -0.11643287f);
    r = fmaf(r, s, 0.19354346f);
    r = fmaf(r, s, -0.33262347f);
    r = fmaf(r, s, 0.99997726f);
    r = r * a;
    r = (y > ax) ? (1.57079632679f - r) : r;
    r = (x < 0.f) ? (3.14159265359f - r) : r;
    return r * 0.31830988618379067f;
}

__device__ __forceinline__ float angle_pi(float axx, float ayy, float azz,
                                          float bxx, float byy, float bzz) {
    float dt = axx * bxx + ayy * byy + azz * bzz;
    float cx = ayy * bzz - azz * byy;
    float cy = azz * bxx - axx * bzz;
    float cz = axx * byy - ayy * bxx;
    float xn = sqrtf(cx * cx + cy * cy + cz * cz);
    return fast_atan2_pi(xn, dt);
}

// ======= Kernel 1: gather-mean + PPF -> L1 -> L2 -> mean -> L3 (fused) =======
#define F_SW1 0
#define F_SB1 256
#define F_SB2 320
#define F_SB3 384
#define F_W2T 448                 // 64 x 68 [i*68+j]
#define F_W3T 4800                // 64 x 68 [i*68+o]
#define F_WARP 9152               // per warp: 576 floats (gather sc / h-stage / hbar)
#define F_SMF (F_WARP + 16 * 576)

__global__ __launch_bounds__(512, 1)
void fused_kernel(const float* __restrict__ q_pts,
                  const float* __restrict__ s_pts,
                  const float* __restrict__ s_feats,
                  const int* __restrict__ nbr,
                  const float* __restrict__ normals,
                  const float* __restrict__ W1, const float* __restrict__ b1,
                  const float* __restrict__ W2, const float* __restrict__ b2,
                  const float* __restrict__ W3, const float* __restrict__ b3) {
    extern __shared__ float sm[];
    const int tid = threadIdx.x;
    for (int i = tid; i < 256; i += 512) sm[F_SW1 + i] = W1[i];
    for (int i = tid; i < 64; i += 512) {
        sm[F_SB1 + i] = b1[i]; sm[F_SB2 + i] = b2[i]; sm[F_SB3 + i] = b3[i];
    }
    for (int l = tid; l < 4096; l += 512) {
        int j = l >> 6, i = l & 63;
        sm[F_W2T + i * 68 + j] = W2[l];
    }
    for (int l = tid; l < 4096; l += 512) {
        int o = l >> 6, i = l & 63;
        sm[F_W3T + i * 68 + o] = W3[l];
    }
    __syncthreads();

    const int w = tid >> 5, lane = tid & 31;
    float* hs = sm + F_WARP + w * 576;   // [16][36] h-stage; gather scratch; hbar
    float* shbf = hs;
    const int j0 = (lane >> 2) * 8;
    const int k0 = (lane & 3) * 8;

    const int o0 = lane * 4;
    const int o1 = (lane < 16) ? (lane + 32) * 4 : (lane - 16) * 4;
    const bool c1a = (lane < 16);
    const int o2 = (lane + 16) * 4;

    int q = blockIdx.x * 16 + w;
    if (q >= NQ) return;
    int idxk = nbr[q * KN + lane];

    for (; q < NQ; q += 148 * 16) {
        const int q_next = q + 148 * 16;
        int idx_next = 0;
        if (q_next < NQ) idx_next = nbr[q_next * KN + lane];

        // ---------------- gather-sum of s_feats over K ----------------
        {
            float4 a0 = {0,0,0,0}, a1 = {0,0,0,0}, a2 = {0,0,0,0};
#pragma unroll 4
            for (int t = 0; t < 16; t++) {
                int ra = __shfl_sync(FULLM, idxk, 2 * t);
                int rb = __shfl_sync(FULLM, idxk, 2 * t + 1);
                const float* pa = s_feats + (size_t)ra * 192;
                const float* pb = s_feats + (size_t)rb * 192;
                float4 v;
                v = *(const float4*)(pa + o0);
                a0.x += v.x; a0.y += v.y; a0.z += v.z; a0.w += v.w;
                v = *(const float4*)((c1a ? pa : pb) + o1);
                a1.x += v.x; a1.y += v.y; a1.z += v.z; a1.w += v.w;
                v = *(const float4*)(pb + o2);
                a2.x += v.x; a2.y += v.y; a2.z += v.z; a2.w += v.w;
            }
            float4* sc4 = (float4*)hs;
            sc4[lane] = a0; sc4[lane + 32] = a1; sc4[lane + 64] = a2;
        }
        __syncwarp();
        {
            const float inv = 1.f / KN;
            float* dst = g_agg + (size_t)q * 192 + lane * 6;
#pragma unroll
            for (int s = 0; s < 3; s++) {
                int f = lane * 6 + 2 * s;
                float v0 = (hs[f] + hs[f + 192]) * inv;
                float v1 = (hs[f + 1] + hs[f + 193]) * inv;
                *(float2*)(dst + 2 * s) = make_float2(v0, v1);
            }
        }
        __syncwarp();

        // ---------------- PPF features ----------------
        const int idx0 = __shfl_sync(FULLM, idxk, 0);
        const float px = q_pts[q * 3 + 0], py = q_pts[q * 3 + 1], pz = q_pts[q * 3 + 2];
        const float pnx = normals[idx0 * 3 + 0], pny = normals[idx0 * 3 + 1], pnz = normals[idx0 * 3 + 2];
        const float sx = s_pts[idxk * 3 + 0], sy = s_pts[idxk * 3 + 1], sz = s_pts[idxk * 3 + 2];
        const float nnx = normals[idxk * 3 + 0], nny = normals[idxk * 3 + 1], nnz = normals[idxk * 3 + 2];

        const float vx = sx - px, vy = sy - py, vz = sz - pz;
        const float dpp = sqrtf(vx * vx + vy * vy + vz * vz);
        const float a1 = angle_pi(pnx, pny, pnz, vx, vy, vz);
        const float a2 = angle_pi(nnx, nny, nnz, vx, vy, vz);
        const float a3 = angle_pi(pnx, pny, pnz, nnx, nny, nnz);

        // ---------------- L2 GEMM: acc[jj][kp], k-pairs packed ----------------
        ull acc[8][4];
#pragma unroll
        for (int jj = 0; jj < 8; jj++) {
            float bv = sm[F_SB2 + j0 + jj];
            ull bp = pk2(bv, bv);
#pragma unroll
            for (int kp = 0; kp < 4; kp++) acc[jj][kp] = bp;
        }

#pragma unroll
        for (int p = 0; p < 4; p++) {
            const float4* w1v = (const float4*)(sm + F_SW1) + p * 16;
            const float* b1p = sm + F_SB1 + p * 16;
#pragma unroll
            for (int ii = 0; ii < 16; ii++) {
                float4 wv = w1v[ii];
                float v = b1p[ii];
                v = fmaf(dpp, wv.x, v);
                v = fmaf(a1, wv.y, v);
                v = fmaf(a2, wv.z, v);
                v = fmaf(a3, wv.w, v);
                hs[ii * 36 + lane] = fmaxf(v, 0.f);
            }
            __syncwarp();
#pragma unroll 4
            for (int ii = 0; ii < 16; ii++) {
                const float* wr = sm + F_W2T + (p * 16 + ii) * 68 + j0;
                float4 wa = *(const float4*)wr;
                float4 wb = *(const float4*)(wr + 4);
                const float* hr = hs + ii * 36 + k0;
                ulonglong2 hA = *(const ulonglong2*)hr;
                ulonglong2 hB = *(const ulonglong2*)(hr + 4);
                ull h0 = hA.x, h1 = hA.y, h2 = hB.x, h3 = hB.y;
                float wvv[8] = {wa.x, wa.y, wa.z, wa.w, wb.x, wb.y, wb.z, wb.w};
#pragma unroll
                for (int jj = 0; jj < 8; jj++) {
                    ull wd = pk2(wvv[jj], wvv[jj]);
                    acc[jj][0] = fma2(wd, h0, acc[jj][0]);
                    acc[jj][1] = fma2(wd, h1, acc[jj][1]);
                    acc[jj][2] = fma2(wd, h2, acc[jj][2]);
                    acc[jj][3] = fma2(wd, h3, acc[jj][3]);
                }
            }
            __syncwarp();
        }

        float o8[8];
#pragma unroll
        for (int jj = 0; jj < 8; jj++) {
            float s = 0.f;
#pragma unroll
            for (int kp = 0; kp < 4; kp++) {
                float lo, hi; upk2(acc[jj][kp], lo, hi);
                s += fmaxf(lo, 0.f) + fmaxf(hi, 0.f);
            }
            o8[jj] = s;
        }
#pragma unroll
        for (int u = 0; u < 8; u++) {
            o8[u] += __shfl_xor_sync(FULLM, o8[u], 1);
            o8[u] += __shfl_xor_sync(FULLM, o8[u], 2);
        }
        if ((lane & 3) == 0) {
            const float inv = 1.f / KN;
#pragma unroll
            for (int u = 0; u < 8; u++) shbf[j0 + u] = o8[u] * inv;
        }
        __syncwarp();

        // L3 on the mean: pm[64] -> global
        {
            float c0 = sm[F_SB3 + lane], c1 = sm[F_SB3 + lane + 32];
#pragma unroll 8
            for (int i = 0; i < 64; i++) {
                float hv = shbf[i];
                c0 = fmaf(hv, sm[F_W3T + i * 68 + lane], c0);
                c1 = fmaf(hv, sm[F_W3T + i * 68 + lane + 32], c1);
            }
            g_pm[q * 64 + lane] = c0;
            g_pm[q * 64 + lane + 32] = c1;
        }
        __syncwarp();
        idxk = idx_next;
    }
}

// ============ Kernel 2a: batched gate -> g_gate (2 CTAs/SM) ============
#define GA_WGT 0                  // 64*196 [j*196+o]
#define GA_BG  12544              // 192
#define GA_PM  12736              // 64*33 [j*33+q]
#define GA_GATE 14848             // 32*197 [q*197+o]
#define GA_SMF 21152              // 84.6 KB

#define GA_GRID 296

__global__ __launch_bounds__(512, 2)
void gate_kernel(const float* __restrict__ Wg, const float* __restrict__ bg) {
    extern __shared__ float sm[];
    const int tid = threadIdx.x;
    for (int l = tid; l < 12288; l += 512) {
        int o = l >> 6, j = l & 63;
        sm[GA_WGT + j * 196 + o] = Wg[l];
    }
    for (int l = tid; l < 192; l += 512) sm[GA_BG + l] = bg[l];
    __syncthreads();

    for (int base = blockIdx.x * 32; base < NQ; base += GA_GRID * 32) {
        // stage pm tile [64 j][32 q]
        {
            const float* psrc = g_pm + (size_t)base * 64;
            for (int e = tid; e < 2048; e += 512) {
                sm[GA_PM + (e & 63) * 33 + (e >> 6)] = psrc[e];
            }
        }
        __syncthreads();

        // gate: thread (q = tid&31, og) -> 12 o
        {
            const int ql = tid & 31, ob2 = (tid >> 5) * 12;
            ull ga[6];
#pragma unroll
            for (int s = 0; s < 6; s++) ga[s] = *(const ull*)(sm + GA_BG + ob2 + 2 * s);
#pragma unroll 4
            for (int j = 0; j < 64; j++) {
                float pv = sm[GA_PM + j * 33 + ql];
                ull pp = pk2(pv, pv);
                const float* wr = sm + GA_WGT + j * 196 + ob2;
                ulonglong2 wA = *(const ulonglong2*)wr;
                ulonglong2 wB = *(const ulonglong2*)(wr + 4);
                ulonglong2 wC = *(const ulonglong2*)(wr + 8);
                ga[0] = fma2(wA.x, pp, ga[0]); ga[1] = fma2(wA.y, pp, ga[1]);
                ga[2] = fma2(wB.x, pp, ga[2]); ga[3] = fma2(wB.y, pp, ga[3]);
                ga[4] = fma2(wC.x, pp, ga[4]); ga[5] = fma2(wC.y, pp, ga[5]);
            }
            float* gr = sm + GA_GATE + ql * 197 + ob2;
#pragma unroll
            for (int s = 0; s < 6; s++) {
                float lo, hi; upk2(ga[s], lo, hi);
                gr[2 * s + 0] = __fdividef(1.f, 1.f + __expf(-lo));
                gr[2 * s + 1] = __fdividef(1.f, 1.f + __expf(-hi));
            }
        }
        __syncthreads();

        // coalesced write to g_gate
        {
            float* gdst = g_gate + (size_t)base * 192;
            for (int e = tid; e < 6144; e += 512) {
                gdst[e] = sm[GA_GATE + (e / 192) * 197 + (e % 192)];
            }
        }
        __syncthreads();
    }
}

// ==== Kernel 2b: Wv GEMM + gate apply + coalesced store (384 thr, 2 CTAs/SM) ====
#define WB_NW 12
#define WB_WVT 0                  // 64*196 [d*196+o]
#define WB_AGG 12544              // 12 warps * 512 floats (256 ull) [d*4+t]
#define WB_SC  18688              // 12 warps * 608 floats
#define WB_SMF 25984              // 103.9 KB

#define WB_GRID 296

__global__ __launch_bounds__(384, 2)
void wv_out_kernel(const float* __restrict__ Wv, float* __restrict__ out) {
    extern __shared__ float sm[];
    const int tid = threadIdx.x;
    for (int l = tid; l < 12288; l += 384) {
        int o = l >> 6, d = l & 63;
        sm[WB_WVT + d * 196 + o] = Wv[l];
    }
    __syncthreads();

    const int w = tid >> 5, lane = tid & 31;
    ull* ag = (ull*)(sm + WB_AGG) + w * 256;
    float* scw = sm + WB_SC + w * 608;
    const int ob = lane * 6;

    for (int base = blockIdx.x * 24; base < NQ; base += WB_GRID * 24) {
        const int q0 = base + w, q1 = base + w + WB_NW;
        const int q0c = (q0 < NQ) ? q0 : (NQ - 1);
        const int q1c = (q1 < NQ) ? q1 : (NQ - 1);

        // stage agg pairs (q0,q1) into ag[d*4+t]
        {
            const float* a0 = g_agg + (size_t)q0c * 192 + lane * 6;
            const float* a1 = g_agg + (size_t)q1c * 192 + lane * 6;
#pragma unroll
            for (int u = 0; u < 6; u++) {
                ag[(2 * lane + u / 3) * 4 + (u % 3)] = pk2(a0[u], a1[u]);
            }
        }
        // load gates (L2-hot)
        float gt0[6], gt1[6];
        {
            const float* p0 = g_gate + (size_t)q0c * 192 + ob;
            const float* p1 = g_gate + (size_t)q1c * 192 + ob;
#pragma unroll
            for (int s = 0; s < 6; s++) { gt0[s] = p0[s]; gt1[s] = p1[s]; }
        }
        __syncwarp();

        // Wv GEMM, (q0,q1) packed in f32x2 lanes
        ull acc2[6][3];
#pragma unroll
        for (int oo = 0; oo < 6; oo++)
#pragma unroll
            for (int t = 0; t < 3; t++) acc2[oo][t] = 0ull;
#pragma unroll 2
        for (int d = 0; d < 64; d++) {
            const float* wp = sm + WB_WVT + d * 196 + ob;
            float2 w01 = *(const float2*)wp;
            float2 w23 = *(const float2*)(wp + 2);
            float2 w45 = *(const float2*)(wp + 4);
            ulonglong2 t01 = *(const ulonglong2*)(ag + d * 4);
            ull t2 = ag[d * 4 + 2];
            float wv6[6] = {w01.x, w01.y, w23.x, w23.y, w45.x, w45.y};
#pragma unroll
            for (int oo = 0; oo < 6; oo++) {
                ull wd = pk2(wv6[oo], wv6[oo]);
                acc2[oo][0] = fma2(wd, t01.x, acc2[oo][0]);
                acc2[oo][1] = fma2(wd, t01.y, acc2[oo][1]);
                acc2[oo][2] = fma2(wd, t2, acc2[oo][2]);
            }
        }

        // q0: stage (19-stride, conflict-free) + coalesced store
        if (q0 < NQ) {
#pragma unroll
            for (int oo = 0; oo < 6; oo++) {
                float x0, x1, y0, y1, z0, z1;
                upk2(acc2[oo][0], x0, x1);
                upk2(acc2[oo][1], y0, y1);
                upk2(acc2[oo][2], z0, z1);
                (void)x1; (void)y1; (void)z1;
                int b = 19 * lane + 3 * oo;
                scw[b + 0] = x0 * gt0[oo];
                scw[b + 1] = y0 * gt0[oo];
                scw[b + 2] = z0 * gt0[oo];
            }
            __syncwarp();
            float* ob0 = out + (size_t)q0 * 576;
#pragma unroll
            for (int i = 0; i < 18; i++) {
                int e = lane + 32 * i;
                ob0[e] = scw[e + e / 18];
            }
        }
        __syncwarp();

        // q1
        if (q1 < NQ) {
#pragma unroll
            for (int oo = 0; oo < 6; oo++) {
                float x0, x1, y0, y1, z0, z1;
                upk2(acc2[oo][0], x0, x1);
                upk2(acc2[oo][1], y0, y1);
                upk2(acc2[oo][2], z0, z1);
                (void)x0; (void)y0; (void)z0;
                int b = 19 * lane + 3 * oo;
                scw[b + 0] = x1 * gt1[oo];
                scw[b + 1] = y1 * gt1[oo];
                scw[b + 2] = z1 * gt1[oo];
            }
            __syncwarp();
            float* ob1 = out + (size_t)q1 * 576;
#pragma unroll
            for (int i = 0; i < 18; i++) {
                int e = lane + 32 * i;
                ob1[e] = scw[e + e / 18];
            }
        }
        __syncwarp();
    }
}

extern "C" void kernel_launch(void* const* d_in, const int* in_sizes, int n_in,
                              void* d_out, int out_size) {
    const float* q_pts   = (const float*)d_in[0];
    const float* s_pts   = (const float*)d_in[1];
    const float* s_feats = (const float*)d_in[2];
    const int*   nbr     = (const int*)  d_in[3];
    const float* normals = (const float*)d_in[4];
    const float* W1 = (const float*)d_in[5];
    const float* b1 = (const float*)d_in[6];
    const float* W2 = (const float*)d_in[7];
    const float* b2 = (const float*)d_in[8];
    const float* W3 = (const float*)d_in[9];
    const float* b3 = (const float*)d_in[10];
    const float* Wg = (const float*)d_in[11];
    const float* bg = (const float*)d_in[12];
    const float* Wv = (const float*)d_in[13];
    float* out = (float*)d_out;

    size_t smem1 = F_SMF * sizeof(float);    // ~73 KB
    size_t smem2a = GA_SMF * sizeof(float);  // ~85 KB
    size_t smem2b = WB_SMF * sizeof(float);  // ~104 KB
    cudaFuncSetAttribute(fused_kernel,
                         cudaFuncAttributeMaxDynamicSharedMemorySize, (int)smem1);
    cudaFuncSetAttribute(gate_kernel,
                         cudaFuncAttributeMaxDynamicSharedMemorySize, (int)smem2a);
    cudaFuncSetAttribute(wv_out_kernel,
                         cudaFuncAttributeMaxDynamicSharedMemorySize, (int)smem2b);

    fused_kernel<<<148, 512, smem1>>>(q_pts, s_pts, s_feats, nbr, normals,
                                      W1, b1, W2, b2, W3, b3);
    gate_kernel<<<GA_GRID, 512, smem2a>>>(Wg, bg);
    wv_out_kernel<<<WB_GRID, 384, smem2b>>>(Wv, out);
}

// round 16
// speedup vs baseline: 2.0294x; 1.2892x over previous
#include <cuda_runtime.h>
#include <math.h>

typedef unsigned long long ull;
typedef unsigned int uint32;

#define NQ 20000
#define KN 32
#define FULLM 0xffffffffu

__device__ float g_pm[NQ * 64];
__device__ float g_agg[NQ * 192];
__device__ float g_gate[NQ * 192];

// ---------- packed f32x2 helpers ----------
__device__ __forceinline__ ull pk2(float lo, float hi) {
    ull r; asm("mov.b64 %0, {%1, %2};" : "=l"(r) : "f"(lo), "f"(hi)); return r;
}
__device__ __forceinline__ void upk2(ull v, float& lo, float& hi) {
    asm("mov.b64 {%0, %1}, %2;" : "=f"(lo), "=f"(hi) : "l"(v));
}
__device__ __forceinline__ ull fma2(ull a, ull b, ull c) {
    ull d; asm("fma.rn.f32x2 %0, %1, %2, %3;" : "=l"(d) : "l"(a), "l"(b), "l"(c)); return d;
}

__device__ __forceinline__ uint32 to_tf32(float v) {
    uint32 u; asm("cvt.rna.tf32.f32 %0, %1;" : "=r"(u) : "f"(v)); return u;
}

// D(16x8) += A(16x8 row tf32) * B(8x8 col tf32)
__device__ __forceinline__ void mma_tf32(float* c, const uint32* a, uint32 b0, uint32 b1) {
    asm volatile(
        "mma.sync.aligned.m16n8k8.row.col.f32.tf32.tf32.f32 "
        "{%0,%1,%2,%3}, {%4,%5,%6,%7}, {%8,%9}, {%0,%1,%2,%3};"
        : "+f"(c[0]), "+f"(c[1]), "+f"(c[2]), "+f"(c[3])
        : "r"(a[0]), "r"(a[1]), "r"(a[2]), "r"(a[3]), "r"(b0), "r"(b1));
}

__device__ __forceinline__ float fast_atan2_pi(float y, float x) {
    float ax = fabsf(x);
    float mx = fmaxf(ax, y);
    float mn = fminf(ax, y);
    float a = __fdividef(mn, fmaxf(mx, 1e-38f));
    float s = a * a;
    float r = -0.01172120f;
    r = fmaf(r, s, 0.05265332f);
    r = fmaf(r, s, -0.11643287f);
    r = fmaf(r, s, 0.19354346f);
    r = fmaf(r, s, -0.33262347f);
    r = fmaf(r, s, 0.99997726f);
    r = r * a;
    r = (y > ax) ? (1.57079632679f - r) : r;
    r = (x < 0.f) ? (3.14159265359f - r) : r;
    return r * 0.31830988618379067f;
}

__device__ __forceinline__ float angle_pi(float axx, float ayy, float azz,
                                          float bxx, float byy, float bzz) {
    float dt = axx * bxx + ayy * byy + azz * bzz;
    float cx = ayy * bzz - azz * byy;
    float cy = azz * bxx - axx * bzz;
    float cz = axx * byy - ayy * bxx;
    float xn = sqrtf(cx * cx + cy * cy + cz * cz);
    return fast_atan2_pi(xn, dt);
}

// ======= Kernel 1: gather-mean + PPF -> L1 -> L2 (tensor core) -> mean -> L3 =======
#define F_SW1 0
#define F_SB1 256
#define F_SB2 320
#define F_SB3 384
#define F_W2F 448                 // 4096: W2 as tf32 B-fragments [(kt*8+nt)*64 + lane*2 + p]
#define F_W3T 4544                // 64 x 68 [i*68+o]
#define F_WARP 8896               // per warp: 2304 floats = h[64][36] (tf32 bits); gather sc; hbar
#define F_WSTRIDE 2304
#define F_SMF (F_WARP + 16 * F_WSTRIDE)   // 45760 floats = 183 KB

__global__ __launch_bounds__(512, 1)
void fused_kernel(const float* __restrict__ q_pts,
                  const float* __restrict__ s_pts,
                  const float* __restrict__ s_feats,
                  const int* __restrict__ nbr,
                  const float* __restrict__ normals,
                  const float* __restrict__ W1, const float* __restrict__ b1,
                  const float* __restrict__ W2, const float* __restrict__ b2,
                  const float* __restrict__ W3, const float* __restrict__ b3) {
    extern __shared__ float sm[];
    const int tid = threadIdx.x;
    for (int i = tid; i < 256; i += 512) sm[F_SW1 + i] = W1[i];
    for (int i = tid; i < 64; i += 512) {
        sm[F_SB1 + i] = b1[i]; sm[F_SB2 + i] = b2[i]; sm[F_SB3 + i] = b3[i];
    }
    // W2 -> tf32 B-fragment layout: b0/b1 for (kt,nt), lane l: j = nt*8 + (l>>2),
    // i = kt*8 + (l&3) + 4*pair
    for (int e = tid; e < 4096; e += 512) {
        int pair = e & 1;
        int l = (e >> 1) & 31;
        int ktnt = e >> 6;
        int kt = ktnt >> 3, nt = ktnt & 7;
        int j = nt * 8 + (l >> 2);
        int i = kt * 8 + (l & 3) + 4 * pair;
        ((uint32*)(sm + F_W2F))[e] = to_tf32(W2[j * 64 + i]);
    }
    for (int l = tid; l < 4096; l += 512) {
        int o = l >> 6, i = l & 63;
        sm[F_W3T + i * 68 + o] = W3[l];
    }
    __syncthreads();

    const int w = tid >> 5, lane = tid & 31;
    float* hs = sm + F_WARP + w * F_WSTRIDE;  // h tf32 bits [i*36 + k]; gather scratch; hbar
    float* shbf = hs;                         // hbar[64] overlays rows 0-1 (reads done by then)
    const int tg = lane & 3;                  // threadID_in_group
    const int gg = lane >> 2;                 // groupID

    const int o0 = lane * 4;
    const int o1 = (lane < 16) ? (lane + 32) * 4 : (lane - 16) * 4;
    const bool c1a = (lane < 16);
    const int o2 = (lane + 16) * 4;

    int q = blockIdx.x * 16 + w;
    if (q >= NQ) return;
    int idxk = nbr[q * KN + lane];

    for (; q < NQ; q += 148 * 16) {
        const int q_next = q + 148 * 16;
        int idx_next = 0;
        if (q_next < NQ) idx_next = nbr[q_next * KN + lane];

        // ---------------- gather-sum of s_feats over K ----------------
        {
            float4 a0 = {0,0,0,0}, a1 = {0,0,0,0}, a2 = {0,0,0,0};
#pragma unroll 4
            for (int t = 0; t < 16; t++) {
                int ra = __shfl_sync(FULLM, idxk, 2 * t);
                int rb = __shfl_sync(FULLM, idxk, 2 * t + 1);
                const float* pa = s_feats + (size_t)ra * 192;
                const float* pb = s_feats + (size_t)rb * 192;
                float4 v;
                v = *(const float4*)(pa + o0);
                a0.x += v.x; a0.y += v.y; a0.z += v.z; a0.w += v.w;
                v = *(const float4*)((c1a ? pa : pb) + o1);
                a1.x += v.x; a1.y += v.y; a1.z += v.z; a1.w += v.w;
                v = *(const float4*)(pb + o2);
                a2.x += v.x; a2.y += v.y; a2.z += v.z; a2.w += v.w;
            }
            float4* sc4 = (float4*)hs;
            sc4[lane] = a0; sc4[lane + 32] = a1; sc4[lane + 64] = a2;
        }
        __syncwarp();
        {
            const float inv = 1.f / KN;
            float* dst = g_agg + (size_t)q * 192 + lane * 6;
#pragma unroll
            for (int s = 0; s < 3; s++) {
                int f = lane * 6 + 2 * s;
                float v0 = (hs[f] + hs[f + 192]) * inv;
                float v1 = (hs[f + 1] + hs[f + 193]) * inv;
                *(float2*)(dst + 2 * s) = make_float2(v0, v1);
            }
        }
        __syncwarp();

        // ---------------- PPF features ----------------
        const int idx0 = __shfl_sync(FULLM, idxk, 0);
        const float px = q_pts[q * 3 + 0], py = q_pts[q * 3 + 1], pz = q_pts[q * 3 + 2];
        const float pnx = normals[idx0 * 3 + 0], pny = normals[idx0 * 3 + 1], pnz = normals[idx0 * 3 + 2];
        const float sx = s_pts[idxk * 3 + 0], sy = s_pts[idxk * 3 + 1], sz = s_pts[idxk * 3 + 2];
        const float nnx = normals[idxk * 3 + 0], nny = normals[idxk * 3 + 1], nnz = normals[idxk * 3 + 2];

        const float vx = sx - px, vy = sy - py, vz = sz - pz;
        const float dpp = sqrtf(vx * vx + vy * vy + vz * vz);
        const float a1 = angle_pi(pnx, pny, pnz, vx, vy, vz);
        const float a2 = angle_pi(nnx, nny, nnz, vx, vy, vz);
        const float a3 = angle_pi(pnx, pny, pnz, nnx, nny, nnz);

        // ---------------- layer1: stage all 64 rows as tf32 bits (lane = k) ----------------
        {
            const float4* w1v = (const float4*)(sm + F_SW1);
            uint32* hsu = (uint32*)hs;
#pragma unroll 8
            for (int ii = 0; ii < 64; ii++) {
                float4 wv = w1v[ii];
                float v = sm[F_SB1 + ii];
                v = fmaf(dpp, wv.x, v);
                v = fmaf(a1, wv.y, v);
                v = fmaf(a2, wv.z, v);
                v = fmaf(a3, wv.w, v);
                hsu[ii * 36 + lane] = to_tf32(fmaxf(v, 0.f));
            }
        }
        __syncwarp();

        // ---------------- L2 GEMM via mma.sync tf32: D[32 k][64 j] ----------------
        // M = k (2 tiles of 16), N = j (8 tiles of 8), K = i (8 tiles of 8)
        float acc[2][8][4];
#pragma unroll
        for (int nt = 0; nt < 8; nt++) {
            float bv0 = sm[F_SB2 + nt * 8 + 2 * tg];
            float bv1 = sm[F_SB2 + nt * 8 + 2 * tg + 1];
#pragma unroll
            for (int mt = 0; mt < 2; mt++) {
                acc[mt][nt][0] = bv0; acc[mt][nt][1] = bv1;
                acc[mt][nt][2] = bv0; acc[mt][nt][3] = bv1;
            }
        }
        {
            const uint32* hsu = (const uint32*)hs;
            const uint32* w2f = (const uint32*)(sm + F_W2F);
#pragma unroll
            for (int kt = 0; kt < 8; kt++) {
                uint32 aF[2][4];
#pragma unroll
                for (int mt = 0; mt < 2; mt++) {
                    int base0 = (kt * 8 + tg) * 36 + mt * 16 + gg;
                    int base1 = base0 + 4 * 36;
                    aF[mt][0] = hsu[base0];        // (row g,   col t)
                    aF[mt][1] = hsu[base0 + 8];    // (row g+8, col t)
                    aF[mt][2] = hsu[base1];        // (row g,   col t+4)
                    aF[mt][3] = hsu[base1 + 8];    // (row g+8, col t+4)
                }
#pragma unroll
                for (int nt = 0; nt < 8; nt++) {
                    uint2 bb = *(const uint2*)(w2f + (kt * 8 + nt) * 64 + lane * 2);
                    mma_tf32(acc[0][nt], aF[0], bb.x, bb.y);
                    mma_tf32(acc[1][nt], aF[1], bb.x, bb.y);
                }
            }
        }
        __syncwarp();   // all h reads done before hbar overlays hs

        // relu + mean over k: sum thread rows, then across the 8 g-lanes
        {
            const float invK = 1.f / KN;
#pragma unroll
            for (int nt = 0; nt < 8; nt++) {
                float s0 = fmaxf(acc[0][nt][0], 0.f) + fmaxf(acc[0][nt][2], 0.f)
                         + fmaxf(acc[1][nt][0], 0.f) + fmaxf(acc[1][nt][2], 0.f);
                float s1 = fmaxf(acc[0][nt][1], 0.f) + fmaxf(acc[0][nt][3], 0.f)
                         + fmaxf(acc[1][nt][1], 0.f) + fmaxf(acc[1][nt][3], 0.f);
                s0 += __shfl_xor_sync(FULLM, s0, 4);
                s0 += __shfl_xor_sync(FULLM, s0, 8);
                s0 += __shfl_xor_sync(FULLM, s0, 16);
                s1 += __shfl_xor_sync(FULLM, s1, 4);
                s1 += __shfl_xor_sync(FULLM, s1, 8);
                s1 += __shfl_xor_sync(FULLM, s1, 16);
                if (gg == 0) {
                    shbf[nt * 8 + 2 * tg] = s0 * invK;
                    shbf[nt * 8 + 2 * tg + 1] = s1 * invK;
                }
            }
        }
        __syncwarp();

        // L3 on the mean: pm[64] -> global
        {
            float c0 = sm[F_SB3 + lane], c1 = sm[F_SB3 + lane + 32];
#pragma unroll 8
            for (int i = 0; i < 64; i++) {
                float hv = shbf[i];
                c0 = fmaf(hv, sm[F_W3T + i * 68 + lane], c0);
                c1 = fmaf(hv, sm[F_W3T + i * 68 + lane + 32], c1);
            }
            g_pm[q * 64 + lane] = c0;
            g_pm[q * 64 + lane + 32] = c1;
        }
        __syncwarp();
        idxk = idx_next;
    }
}

// ============ Kernel 2a: batched gate -> g_gate (2 CTAs/SM) ============
#define GA_WGT 0                  // 64*196 [j*196+o]
#define GA_BG  12544              // 192
#define GA_PM  12736              // 64*33 [j*33+q]
#define GA_GATE 14848             // 32*197 [q*197+o]
#define GA_SMF 21152              // 84.6 KB

#define GA_GRID 296

__global__ __launch_bounds__(512, 2)
void gate_kernel(const float* __restrict__ Wg, const float* __restrict__ bg) {
    extern __shared__ float sm[];
    const int tid = threadIdx.x;
    for (int l = tid; l < 12288; l += 512) {
        int o = l >> 6, j = l & 63;
        sm[GA_WGT + j * 196 + o] = Wg[l];
    }
    for (int l = tid; l < 192; l += 512) sm[GA_BG + l] = bg[l];
    __syncthreads();

    for (int base = blockIdx.x * 32; base < NQ; base += GA_GRID * 32) {
        {
            const float* psrc = g_pm + (size_t)base * 64;
            for (int e = tid; e < 2048; e += 512) {
                sm[GA_PM + (e & 63) * 33 + (e >> 6)] = psrc[e];
            }
        }
        __syncthreads();

        {
            const int ql = tid & 31, ob2 = (tid >> 5) * 12;
            ull ga[6];
#pragma unroll
            for (int s = 0; s < 6; s++) ga[s] = *(const ull*)(sm + GA_BG + ob2 + 2 * s);
#pragma unroll 4
            for (int j = 0; j < 64; j++) {
                float pv = sm[GA_PM + j * 33 + ql];
                ull pp = pk2(pv, pv);
                const float* wr = sm + GA_WGT + j * 196 + ob2;
                ulonglong2 wA = *(const ulonglong2*)wr;
                ulonglong2 wB = *(const ulonglong2*)(wr + 4);
                ulonglong2 wC = *(const ulonglong2*)(wr + 8);
                ga[0] = fma2(wA.x, pp, ga[0]); ga[1] = fma2(wA.y, pp, ga[1]);
                ga[2] = fma2(wB.x, pp, ga[2]); ga[3] = fma2(wB.y, pp, ga[3]);
                ga[4] = fma2(wC.x, pp, ga[4]); ga[5] = fma2(wC.y, pp, ga[5]);
            }
            float* gr = sm + GA_GATE + ql * 197 + ob2;
#pragma unroll
            for (int s = 0; s < 6; s++) {
                float lo, hi; upk2(ga[s], lo, hi);
                gr[2 * s + 0] = __fdividef(1.f, 1.f + __expf(-lo));
                gr[2 * s + 1] = __fdividef(1.f, 1.f + __expf(-hi));
            }
        }
        __syncthreads();

        {
            float* gdst = g_gate + (size_t)base * 192;
            for (int e = tid; e < 6144; e += 512) {
                gdst[e] = sm[GA_GATE + (e / 192) * 197 + (e % 192)];
            }
        }
        __syncthreads();
    }
}

// ==== Kernel 2b: Wv GEMM + gate apply + coalesced store (384 thr, 2 CTAs/SM) ====
#define WB_NW 12
#define WB_WVT 0                  // 64*196 [d*196+o]
#define WB_AGG 12544              // 12 warps * 512 floats (256 ull) [d*4+t]
#define WB_SC  18688              // 12 warps * 608 floats
#define WB_SMF 25984              // 103.9 KB

#define WB_GRID 296

__global__ __launch_bounds__(384, 2)
void wv_out_kernel(const float* __restrict__ Wv, float* __restrict__ out) {
    extern __shared__ float sm[];
    const int tid = threadIdx.x;
    for (int l = tid; l < 12288; l += 384) {
        int o = l >> 6, d = l & 63;
        sm[WB_WVT + d * 196 + o] = Wv[l];
    }
    __syncthreads();

    const int w = tid >> 5, lane = tid & 31;
    ull* ag = (ull*)(sm + WB_AGG) + w * 256;
    float* scw = sm + WB_SC + w * 608;
    const int ob = lane * 6;

    for (int base = blockIdx.x * 24; base < NQ; base += WB_GRID * 24) {
        const int q0 = base + w, q1 = base + w + WB_NW;
        const int q0c = (q0 < NQ) ? q0 : (NQ - 1);
        const int q1c = (q1 < NQ) ? q1 : (NQ - 1);

        {
            const float* a0 = g_agg + (size_t)q0c * 192 + lane * 6;
            const float* a1 = g_agg + (size_t)q1c * 192 + lane * 6;
#pragma unroll
            for (int u = 0; u < 6; u++) {
                ag[(2 * lane + u / 3) * 4 + (u % 3)] = pk2(a0[u], a1[u]);
            }
        }
        float gt0[6], gt1[6];
        {
            const float* p0 = g_gate + (size_t)q0c * 192 + ob;
            const float* p1 = g_gate + (size_t)q1c * 192 + ob;
#pragma unroll
            for (int s = 0; s < 6; s++) { gt0[s] = p0[s]; gt1[s] = p1[s]; }
        }
        __syncwarp();

        ull acc2[6][3];
#pragma unroll
        for (int oo = 0; oo < 6; oo++)
#pragma unroll
            for (int t = 0; t < 3; t++) acc2[oo][t] = 0ull;
#pragma unroll 2
        for (int d = 0; d < 64; d++) {
            const float* wp = sm + WB_WVT + d * 196 + ob;
            float2 w01 = *(const float2*)wp;
            float2 w23 = *(const float2*)(wp + 2);
            float2 w45 = *(const float2*)(wp + 4);
            ulonglong2 t01 = *(const ulonglong2*)(ag + d * 4);
            ull t2 = ag[d * 4 + 2];
            float wv6[6] = {w01.x, w01.y, w23.x, w23.y, w45.x, w45.y};
#pragma unroll
            for (int oo = 0; oo < 6; oo++) {
                ull wd = pk2(wv6[oo], wv6[oo]);
                acc2[oo][0] = fma2(wd, t01.x, acc2[oo][0]);
                acc2[oo][1] = fma2(wd, t01.y, acc2[oo][1]);
                acc2[oo][2] = fma2(wd, t2, acc2[oo][2]);
            }
        }

        if (q0 < NQ) {
#pragma unroll
            for (int oo = 0; oo < 6; oo++) {
                float x0, x1, y0, y1, z0, z1;
                upk2(acc2[oo][0], x0, x1);
                upk2(acc2[oo][1], y0, y1);
                upk2(acc2[oo][2], z0, z1);
                (void)x1; (void)y1; (void)z1;
                int b = 19 * lane + 3 * oo;
                scw[b + 0] = x0 * gt0[oo];
                scw[b + 1] = y0 * gt0[oo];
                scw[b + 2] = z0 * gt0[oo];
            }
            __syncwarp();
            float* ob0 = out + (size_t)q0 * 576;
#pragma unroll
            for (int i = 0; i < 18; i++) {
                int e = lane + 32 * i;
                ob0[e] = scw[e + e / 18];
            }
        }
        __syncwarp();

        if (q1 < NQ) {
#pragma unroll
            for (int oo = 0; oo < 6; oo++) {
                float x0, x1, y0, y1, z0, z1;
                upk2(acc2[oo][0], x0, x1);
                upk2(acc2[oo][1], y0, y1);
                upk2(acc2[oo][2], z0, z1);
                (void)x0; (void)y0; (void)z0;
                int b = 19 * lane + 3 * oo;
                scw[b + 0] = x1 * gt1[oo];
                scw[b + 1] = y1 * gt1[oo];
                scw[b + 2] = z1 * gt1[oo];
            }
            __syncwarp();
            float* ob1 = out + (size_t)q1 * 576;
#pragma unroll
            for (int i = 0; i < 18; i++) {
                int e = lane + 32 * i;
                ob1[e] = scw[e + e / 18];
            }
        }
        __syncwarp();
    }
}

extern "C" void kernel_launch(void* const* d_in, const int* in_sizes, int n_in,
                              void* d_out, int out_size) {
    const float* q_pts   = (const float*)d_in[0];
    const float* s_pts   = (const float*)d_in[1];
    const float* s_feats = (const float*)d_in[2];
    const int*   nbr     = (const int*)  d_in[3];
    const float* normals = (const float*)d_in[4];
    const float* W1 = (const float*)d_in[5];
    const float* b1 = (const float*)d_in[6];
    const float* W2 = (const float*)d_in[7];
    const float* b2 = (const float*)d_in[8];
    const float* W3 = (const float*)d_in[9];
    const float* b3 = (const float*)d_in[10];
    const float* Wg = (const float*)d_in[11];
    const float* bg = (const float*)d_in[12];
    const float* Wv = (const float*)d_in[13];
    float* out = (float*)d_out;

    size_t smem1 = F_SMF * sizeof(float);    // ~183 KB
    size_t smem2a = GA_SMF * sizeof(float);  // ~85 KB
    size_t smem2b = WB_SMF * sizeof(float);  // ~104 KB
    cudaFuncSetAttribute(fused_kernel,
                         cudaFuncAttributeMaxDynamicSharedMemorySize, (int)smem1);
    cudaFuncSetAttribute(gate_kernel,
                         cudaFuncAttributeMaxDynamicSharedMemorySize, (int)smem2a);
    cudaFuncSetAttribute(wv_out_kernel,
                         cudaFuncAttributeMaxDynamicSharedMemorySize, (int)smem2b);

    fused_kernel<<<148, 512, smem1>>>(q_pts, s_pts, s_feats, nbr, normals,
                                      W1, b1, W2, b2, W3, b3);
    gate_kernel<<<GA_GRID, 512, smem2a>>>(Wg, bg);
    wv_out_kernel<<<WB_GRID, 384, smem2b>>>(Wv, out);
}

// round 17
// speedup vs baseline: 2.1382x; 1.0536x over previous
#include <cuda_runtime.h>
#include <math.h>

typedef unsigned long long ull;
typedef unsigned int uint32;

#define NQ 20000
#define KN 32
#define FULLM 0xffffffffu

__device__ float g_pm[NQ * 64];
__device__ float g_agg[NQ * 192];
__device__ float g_gate[NQ * 192];

// ---------- packed f32x2 helpers ----------
__device__ __forceinline__ ull pk2(float lo, float hi) {
    ull r; asm("mov.b64 %0, {%1, %2};" : "=l"(r) : "f"(lo), "f"(hi)); return r;
}
__device__ __forceinline__ void upk2(ull v, float& lo, float& hi) {
    asm("mov.b64 {%0, %1}, %2;" : "=f"(lo), "=f"(hi) : "l"(v));
}
__device__ __forceinline__ ull fma2(ull a, ull b, ull c) {
    ull d; asm("fma.rn.f32x2 %0, %1, %2, %3;" : "=l"(d) : "l"(a), "l"(b), "l"(c)); return d;
}

__device__ __forceinline__ uint32 to_tf32(float v) {
    uint32 u; asm("cvt.rna.tf32.f32 %0, %1;" : "=r"(u) : "f"(v)); return u;
}

// D(16x8) += A(16x8 row tf32) * B(8x8 col tf32)
__device__ __forceinline__ void mma_tf32(float* c, const uint32* a, uint32 b0, uint32 b1) {
    asm volatile(
        "mma.sync.aligned.m16n8k8.row.col.f32.tf32.tf32.f32 "
        "{%0,%1,%2,%3}, {%4,%5,%6,%7}, {%8,%9}, {%0,%1,%2,%3};"
        : "+f"(c[0]), "+f"(c[1]), "+f"(c[2]), "+f"(c[3])
        : "r"(a[0]), "r"(a[1]), "r"(a[2]), "r"(a[3]), "r"(b0), "r"(b1));
}

__device__ __forceinline__ float fast_atan2_pi(float y, float x) {
    float ax = fabsf(x);
    float mx = fmaxf(ax, y);
    float mn = fminf(ax, y);
    float a = __fdividef(mn, fmaxf(mx, 1e-38f));
    float s = a * a;
    float r = -0.01172120f;
    r = fmaf(r, s, 0.05265332f);
    r = fmaf(r, s, -0.11643287f);
    r = fmaf(r, s, 0.19354346f);
    r = fmaf(r, s, -0.33262347f);
    r = fmaf(r, s, 0.99997726f);
    r = r * a;
    r = (y > ax) ? (1.57079632679f - r) : r;
    r = (x < 0.f) ? (3.14159265359f - r) : r;
    return r * 0.31830988618379067f;
}

__device__ __forceinline__ float angle_pi(float axx, float ayy, float azz,
                                          float bxx, float byy, float bzz) {
    float dt = axx * bxx + ayy * byy + azz * bzz;
    float cx = ayy * bzz - azz * byy;
    float cy = azz * bxx - axx * bzz;
    float cz = axx * byy - ayy * bxx;
    float xn = sqrtf(cx * cx + cy * cy + cz * cz);
    return fast_atan2_pi(xn, dt);
}

// ======= Kernel 1: gather-mean + PPF -> L1 -> L2 (tensor core) -> mean -> L3 =======
#define F_SW1 0
#define F_SB1 256
#define F_SB2 320
#define F_SB3 384
#define F_W2F 448                 // 4096: W2 as tf32 B-fragments [(kt*8+nt)*64 + lane*2 + p]
#define F_W3T 4544                // 64 x 68 [i*68+o]
#define F_WARP 8896               // per warp: 2304 floats = h[64][36] (tf32 bits); gather sc; hbar
#define F_WSTRIDE 2304
#define F_SMF (F_WARP + 16 * F_WSTRIDE)   // 45760 floats = 183 KB

__global__ __launch_bounds__(512, 1)
void fused_kernel(const float* __restrict__ q_pts,
                  const float* __restrict__ s_pts,
                  const float* __restrict__ s_feats,
                  const int* __restrict__ nbr,
                  const float* __restrict__ normals,
                  const float* __restrict__ W1, const float* __restrict__ b1,
                  const float* __restrict__ W2, const float* __restrict__ b2,
                  const float* __restrict__ W3, const float* __restrict__ b3) {
    extern __shared__ float sm[];
    const int tid = threadIdx.x;
    for (int i = tid; i < 256; i += 512) sm[F_SW1 + i] = W1[i];
    for (int i = tid; i < 64; i += 512) {
        sm[F_SB1 + i] = b1[i]; sm[F_SB2 + i] = b2[i]; sm[F_SB3 + i] = b3[i];
    }
    for (int e = tid; e < 4096; e += 512) {
        int pair = e & 1;
        int l = (e >> 1) & 31;
        int ktnt = e >> 6;
        int kt = ktnt >> 3, nt = ktnt & 7;
        int j = nt * 8 + (l >> 2);
        int i = kt * 8 + (l & 3) + 4 * pair;
        ((uint32*)(sm + F_W2F))[e] = to_tf32(W2[j * 64 + i]);
    }
    for (int l = tid; l < 4096; l += 512) {
        int o = l >> 6, i = l & 63;
        sm[F_W3T + i * 68 + o] = W3[l];
    }
    __syncthreads();

    const int w = tid >> 5, lane = tid & 31;
    float* hs = sm + F_WARP + w * F_WSTRIDE;
    float* shbf = hs;
    const int tg = lane & 3;
    const int gg = lane >> 2;

    const int o0 = lane * 4;
    const int o1 = (lane < 16) ? (lane + 32) * 4 : (lane - 16) * 4;
    const bool c1a = (lane < 16);
    const int o2 = (lane + 16) * 4;

    int q = blockIdx.x * 16 + w;
    if (q >= NQ) return;
    int idxk = nbr[q * KN + lane];

    for (; q < NQ; q += 148 * 16) {
        const int q_next = q + 148 * 16;
        int idx_next = 0;
        if (q_next < NQ) idx_next = nbr[q_next * KN + lane];

        // gather-sum of s_feats over K
        {
            float4 a0 = {0,0,0,0}, a1 = {0,0,0,0}, a2 = {0,0,0,0};
#pragma unroll 4
            for (int t = 0; t < 16; t++) {
                int ra = __shfl_sync(FULLM, idxk, 2 * t);
                int rb = __shfl_sync(FULLM, idxk, 2 * t + 1);
                const float* pa = s_feats + (size_t)ra * 192;
                const float* pb = s_feats + (size_t)rb * 192;
                float4 v;
                v = *(const float4*)(pa + o0);
                a0.x += v.x; a0.y += v.y; a0.z += v.z; a0.w += v.w;
                v = *(const float4*)((c1a ? pa : pb) + o1);
                a1.x += v.x; a1.y += v.y; a1.z += v.z; a1.w += v.w;
                v = *(const float4*)(pb + o2);
                a2.x += v.x; a2.y += v.y; a2.z += v.z; a2.w += v.w;
            }
            float4* sc4 = (float4*)hs;
            sc4[lane] = a0; sc4[lane + 32] = a1; sc4[lane + 64] = a2;
        }
        __syncwarp();
        {
            const float inv = 1.f / KN;
            float* dst = g_agg + (size_t)q * 192 + lane * 6;
#pragma unroll
            for (int s = 0; s < 3; s++) {
                int f = lane * 6 + 2 * s;
                float v0 = (hs[f] + hs[f + 192]) * inv;
                float v1 = (hs[f + 1] + hs[f + 193]) * inv;
                *(float2*)(dst + 2 * s) = make_float2(v0, v1);
            }
        }
        __syncwarp();

        // PPF features
        const int idx0 = __shfl_sync(FULLM, idxk, 0);
        const float px = q_pts[q * 3 + 0], py = q_pts[q * 3 + 1], pz = q_pts[q * 3 + 2];
        const float pnx = normals[idx0 * 3 + 0], pny = normals[idx0 * 3 + 1], pnz = normals[idx0 * 3 + 2];
        const float sx = s_pts[idxk * 3 + 0], sy = s_pts[idxk * 3 + 1], sz = s_pts[idxk * 3 + 2];
        const float nnx = normals[idxk * 3 + 0], nny = normals[idxk * 3 + 1], nnz = normals[idxk * 3 + 2];

        const float vx = sx - px, vy = sy - py, vz = sz - pz;
        const float dpp = sqrtf(vx * vx + vy * vy + vz * vz);
        const float a1 = angle_pi(pnx, pny, pnz, vx, vy, vz);
        const float a2 = angle_pi(nnx, nny, nnz, vx, vy, vz);
        const float a3 = angle_pi(pnx, pny, pnz, nnx, nny, nnz);

        // layer1: stage all 64 rows as tf32 bits (lane = k)
        {
            const float4* w1v = (const float4*)(sm + F_SW1);
            uint32* hsu = (uint32*)hs;
#pragma unroll 8
            for (int ii = 0; ii < 64; ii++) {
                float4 wv = w1v[ii];
                float v = sm[F_SB1 + ii];
                v = fmaf(dpp, wv.x, v);
                v = fmaf(a1, wv.y, v);
                v = fmaf(a2, wv.z, v);
                v = fmaf(a3, wv.w, v);
                hsu[ii * 36 + lane] = to_tf32(fmaxf(v, 0.f));
            }
        }
        __syncwarp();

        // L2 GEMM via mma.sync tf32: D[32 k][64 j]
        float acc[2][8][4];
#pragma unroll
        for (int nt = 0; nt < 8; nt++) {
            float bv0 = sm[F_SB2 + nt * 8 + 2 * tg];
            float bv1 = sm[F_SB2 + nt * 8 + 2 * tg + 1];
#pragma unroll
            for (int mt = 0; mt < 2; mt++) {
                acc[mt][nt][0] = bv0; acc[mt][nt][1] = bv1;
                acc[mt][nt][2] = bv0; acc[mt][nt][3] = bv1;
            }
        }
        {
            const uint32* hsu = (const uint32*)hs;
            const uint32* w2f = (const uint32*)(sm + F_W2F);
#pragma unroll
            for (int kt = 0; kt < 8; kt++) {
                uint32 aF[2][4];
#pragma unroll
                for (int mt = 0; mt < 2; mt++) {
                    int base0 = (kt * 8 + tg) * 36 + mt * 16 + gg;
                    int base1 = base0 + 4 * 36;
                    aF[mt][0] = hsu[base0];
                    aF[mt][1] = hsu[base0 + 8];
                    aF[mt][2] = hsu[base1];
                    aF[mt][3] = hsu[base1 + 8];
                }
#pragma unroll
                for (int nt = 0; nt < 8; nt++) {
                    uint2 bb = *(const uint2*)(w2f + (kt * 8 + nt) * 64 + lane * 2);
                    mma_tf32(acc[0][nt], aF[0], bb.x, bb.y);
                    mma_tf32(acc[1][nt], aF[1], bb.x, bb.y);
                }
            }
        }
        __syncwarp();

        // relu + mean over k
        {
            const float invK = 1.f / KN;
#pragma unroll
            for (int nt = 0; nt < 8; nt++) {
                float s0 = fmaxf(acc[0][nt][0], 0.f) + fmaxf(acc[0][nt][2], 0.f)
                         + fmaxf(acc[1][nt][0], 0.f) + fmaxf(acc[1][nt][2], 0.f);
                float s1 = fmaxf(acc[0][nt][1], 0.f) + fmaxf(acc[0][nt][3], 0.f)
                         + fmaxf(acc[1][nt][1], 0.f) + fmaxf(acc[1][nt][3], 0.f);
                s0 += __shfl_xor_sync(FULLM, s0, 4);
                s0 += __shfl_xor_sync(FULLM, s0, 8);
                s0 += __shfl_xor_sync(FULLM, s0, 16);
                s1 += __shfl_xor_sync(FULLM, s1, 4);
                s1 += __shfl_xor_sync(FULLM, s1, 8);
                s1 += __shfl_xor_sync(FULLM, s1, 16);
                if (gg == 0) {
                    shbf[nt * 8 + 2 * tg] = s0 * invK;
                    shbf[nt * 8 + 2 * tg + 1] = s1 * invK;
                }
            }
        }
        __syncwarp();

        // L3 on the mean: pm[64] -> global
        {
            float c0 = sm[F_SB3 + lane], c1 = sm[F_SB3 + lane + 32];
#pragma unroll 8
            for (int i = 0; i < 64; i++) {
                float hv = shbf[i];
                c0 = fmaf(hv, sm[F_W3T + i * 68 + lane], c0);
                c1 = fmaf(hv, sm[F_W3T + i * 68 + lane + 32], c1);
            }
            g_pm[q * 64 + lane] = c0;
            g_pm[q * 64 + lane + 32] = c1;
        }
        __syncwarp();
        idxk = idx_next;
    }
}

// ===== Kernel 2a: gate via mma.sync tf32 (D[192 o][32 q] per tile) -> g_gate =====
// A = Wg (M=192, K=64) as tf32 fragments; B = pm tile (K=64, N=32), stride-41 tf32
#define GA_WGF 0                  // 12288 u32: [(mt*8+kt)*128 + lane*4 + r]
#define GA_BG  12288              // 192
#define GA_PM  12480              // 64*41 tf32 [j*41 + q]
#define GA_SMF 15104              // 60.4 KB

#define GA_GRID 296

__global__ __launch_bounds__(512, 2)
void gate_kernel(const float* __restrict__ Wg, const float* __restrict__ bg) {
    extern __shared__ float sm[];
    const int tid = threadIdx.x;
    // Wg -> A-fragment blocks: block (mt,kt); lane l=(gg,tg); r in [0,4)
    for (int e = tid; e < 12288; e += 512) {
        int r = e & 3;
        int l = (e >> 2) & 31;
        int blk = e >> 7;
        int mt = blk >> 3, kt = blk & 7;
        int gg = l >> 2, tg = l & 3;
        int o = mt * 16 + gg + 8 * (r & 1);
        int j = kt * 8 + tg + 4 * (r >> 1);
        ((uint32*)(sm + GA_WGF))[e] = to_tf32(Wg[o * 64 + j]);
    }
    for (int l = tid; l < 192; l += 512) sm[GA_BG + l] = bg[l];
    __syncthreads();

    const int w = tid >> 5, lane = tid & 31;
    const int tg = lane & 3, gg = lane >> 2;
    const int nt = w & 3;
    const int mtb = w >> 2;   // mt = mtb, mtb+4, mtb+8

    for (int base = blockIdx.x * 32; base < NQ; base += GA_GRID * 32) {
        // stage pm tile as tf32 [j*41 + q]  (coalesced read; conflict-free write)
        {
            const float* psrc = g_pm + (size_t)base * 64;
            uint32* pmu = (uint32*)(sm + GA_PM);
            for (int e = tid; e < 2048; e += 512) {
                int qq = e >> 6, j = e & 63;
                pmu[j * 41 + qq] = to_tf32(psrc[e]);
            }
        }
        __syncthreads();

        // GEMM: warp covers (nt, {mtb, mtb+4, mtb+8})
        float acc[3][4];
#pragma unroll
        for (int t3 = 0; t3 < 3; t3++) {
            int mt = mtb + 4 * t3;
            float b0v = sm[GA_BG + mt * 16 + gg];
            float b1v = sm[GA_BG + mt * 16 + gg + 8];
            acc[t3][0] = b0v; acc[t3][1] = b0v;
            acc[t3][2] = b1v; acc[t3][3] = b1v;
        }
        {
            const uint32* pmu = (const uint32*)(sm + GA_PM);
            const uint32* wgf = (const uint32*)(sm + GA_WGF);
#pragma unroll
            for (int kt = 0; kt < 8; kt++) {
                uint32 b0 = pmu[(kt * 8 + tg) * 41 + nt * 8 + gg];
                uint32 b1 = pmu[(kt * 8 + tg + 4) * 41 + nt * 8 + gg];
#pragma unroll
                for (int t3 = 0; t3 < 3; t3++) {
                    int mt = mtb + 4 * t3;
                    uint4 av = *(const uint4*)(wgf + ((mt * 8 + kt) << 7) + lane * 4);
                    uint32 aF[4] = {av.x, av.y, av.z, av.w};
                    mma_tf32(acc[t3], aF, b0, b1);
                }
            }
        }

        // sigmoid + store: c0=(gg,2tg) c1=(gg,2tg+1) c2=(gg+8,2tg) c3=(gg+8,2tg+1)
        {
            const int q0 = base + nt * 8 + 2 * tg;
#pragma unroll
            for (int t3 = 0; t3 < 3; t3++) {
                int mt = mtb + 4 * t3;
                int oo = mt * 16 + gg;
                float g0 = __fdividef(1.f, 1.f + __expf(-acc[t3][0]));
                float g1 = __fdividef(1.f, 1.f + __expf(-acc[t3][1]));
                float g2 = __fdividef(1.f, 1.f + __expf(-acc[t3][2]));
                float g3 = __fdividef(1.f, 1.f + __expf(-acc[t3][3]));
                g_gate[(size_t)q0 * 192 + oo] = g0;
                g_gate[(size_t)(q0 + 1) * 192 + oo] = g1;
                g_gate[(size_t)q0 * 192 + oo + 8] = g2;
                g_gate[(size_t)(q0 + 1) * 192 + oo + 8] = g3;
            }
        }
        __syncthreads();   // pm tile reads done before next stage overwrites
    }
}

// ==== Kernel 2b: Wv GEMM + gate apply + coalesced store (384 thr, 2 CTAs/SM) ====
#define WB_NW 12
#define WB_WVT 0                  // 64*196 [d*196+o]
#define WB_AGG 12544              // 12 warps * 512 floats (256 ull) [d*4+t]
#define WB_SC  18688              // 12 warps * 608 floats
#define WB_SMF 25984              // 103.9 KB

#define WB_GRID 296

__global__ __launch_bounds__(384, 2)
void wv_out_kernel(const float* __restrict__ Wv, float* __restrict__ out) {
    extern __shared__ float sm[];
    const int tid = threadIdx.x;
    for (int l = tid; l < 12288; l += 384) {
        int o = l >> 6, d = l & 63;
        sm[WB_WVT + d * 196 + o] = Wv[l];
    }
    __syncthreads();

    const int w = tid >> 5, lane = tid & 31;
    ull* ag = (ull*)(sm + WB_AGG) + w * 256;
    float* scw = sm + WB_SC + w * 608;
    const int ob = lane * 6;

    for (int base = blockIdx.x * 24; base < NQ; base += WB_GRID * 24) {
        const int q0 = base + w, q1 = base + w + WB_NW;
        const int q0c = (q0 < NQ) ? q0 : (NQ - 1);
        const int q1c = (q1 < NQ) ? q1 : (NQ - 1);

        {
            const float* a0 = g_agg + (size_t)q0c * 192 + lane * 6;
            const float* a1 = g_agg + (size_t)q1c * 192 + lane * 6;
#pragma unroll
            for (int u = 0; u < 6; u++) {
                ag[(2 * lane + u / 3) * 4 + (u % 3)] = pk2(a0[u], a1[u]);
            }
        }
        float gt0[6], gt1[6];
        {
            const float* p0 = g_gate + (size_t)q0c * 192 + ob;
            const float* p1 = g_gate + (size_t)q1c * 192 + ob;
#pragma unroll
            for (int s = 0; s < 6; s++) { gt0[s] = p0[s]; gt1[s] = p1[s]; }
        }
        __syncwarp();

        ull acc2[6][3];
#pragma unroll
        for (int oo = 0; oo < 6; oo++)
#pragma unroll
            for (int t = 0; t < 3; t++) acc2[oo][t] = 0ull;
#pragma unroll 2
        for (int d = 0; d < 64; d++) {
            const float* wp = sm + WB_WVT + d * 196 + ob;
            float2 w01 = *(const float2*)wp;
            float2 w23 = *(const float2*)(wp + 2);
            float2 w45 = *(const float2*)(wp + 4);
            ulonglong2 t01 = *(const ulonglong2*)(ag + d * 4);
            ull t2 = ag[d * 4 + 2];
            float wv6[6] = {w01.x, w01.y, w23.x, w23.y, w45.x, w45.y};
#pragma unroll
            for (int oo = 0; oo < 6; oo++) {
                ull wd = pk2(wv6[oo], wv6[oo]);
                acc2[oo][0] = fma2(wd, t01.x, acc2[oo][0]);
                acc2[oo][1] = fma2(wd, t01.y, acc2[oo][1]);
                acc2[oo][2] = fma2(wd, t2, acc2[oo][2]);
            }
        }

        if (q0 < NQ) {
#pragma unroll
            for (int oo = 0; oo < 6; oo++) {
                float x0, x1, y0, y1, z0, z1;
                upk2(acc2[oo][0], x0, x1);
                upk2(acc2[oo][1], y0, y1);
                upk2(acc2[oo][2], z0, z1);
                (void)x1; (void)y1; (void)z1;
                int b = 19 * lane + 3 * oo;
                scw[b + 0] = x0 * gt0[oo];
                scw[b + 1] = y0 * gt0[oo];
                scw[b + 2] = z0 * gt0[oo];
            }
            __syncwarp();
            float* ob0 = out + (size_t)q0 * 576;
#pragma unroll
            for (int i = 0; i < 18; i++) {
                int e = lane + 32 * i;
                ob0[e] = scw[e + e / 18];
            }
        }
        __syncwarp();

        if (q1 < NQ) {
#pragma unroll
            for (int oo = 0; oo < 6; oo++) {
                float x0, x1, y0, y1, z0, z1;
                upk2(acc2[oo][0], x0, x1);
                upk2(acc2[oo][1], y0, y1);
                upk2(acc2[oo][2], z0, z1);
                (void)x0; (void)y0; (void)z0;
                int b = 19 * lane + 3 * oo;
                scw[b + 0] = x1 * gt1[oo];
                scw[b + 1] = y1 * gt1[oo];
                scw[b + 2] = z1 * gt1[oo];
            }
            __syncwarp();
            float* ob1 = out + (size_t)q1 * 576;
#pragma unroll
            for (int i = 0; i < 18; i++) {
                int e = lane + 32 * i;
                ob1[e] = scw[e + e / 18];
            }
        }
        __syncwarp();
    }
}

extern "C" void kernel_launch(void* const* d_in, const int* in_sizes, int n_in,
                              void* d_out, int out_size) {
    const float* q_pts   = (const float*)d_in[0];
    const float* s_pts   = (const float*)d_in[1];
    const float* s_feats = (const float*)d_in[2];
    const int*   nbr     = (const int*)  d_in[3];
    const float* normals = (const float*)d_in[4];
    const float* W1 = (const float*)d_in[5];
    const float* b1 = (const float*)d_in[6];
    const float* W2 = (const float*)d_in[7];
    const float* b2 = (const float*)d_in[8];
    const float* W3 = (const float*)d_in[9];
    const float* b3 = (const float*)d_in[10];
    const float* Wg = (const float*)d_in[11];
    const float* bg = (const float*)d_in[12];
    const float* Wv = (const float*)d_in[13];
    float* out = (float*)d_out;

    size_t smem1 = F_SMF * sizeof(float);    // ~183 KB
    size_t smem2a = GA_SMF * sizeof(float);  // ~60.4 KB
    size_t smem2b = WB_SMF * sizeof(float);  // ~104 KB
    cudaFuncSetAttribute(fused_kernel,
                         cudaFuncAttributeMaxDynamicSharedMemorySize, (int)smem1);
    cudaFuncSetAttribute(gate_kernel,
                         cudaFuncAttributeMaxDynamicSharedMemorySize, (int)smem2a);
    cudaFuncSetAttribute(wv_out_kernel,
                         cudaFuncAttributeMaxDynamicSharedMemorySize, (int)smem2b);

    fused_kernel<<<148, 512, smem1>>>(q_pts, s_pts, s_feats, nbr, normals,
                                      W1, b1, W2, b2, W3, b3);
    gate_kernel<<<GA_GRID, 512, smem2a>>>(Wg, bg);
    wv_out_kernel<<<WB_GRID, 384, smem2b>>>(Wv, out);
}